// round 17
// baseline (speedup 1.0000x reference)
#include <cuda_runtime.h>
#include <cuda_bf16.h>
#include <cstdint>

// Problem constants
#define B_ 256
#define H_ 512
#define C_ 64
#define NKNOTS 100
#define KTERMS 8

#define TPB 256
#define NCTA 128
#define NROWG 8            // row groups (blockIdx.x)
#define RG_CTAS 16         // CTAs per row group (gridDim.y)
#define GTH (NCTA * TPB)

typedef __nv_bfloat16 bf16;

// ---------------- smem layout (dynamic): resident W tiles only ----------------
#define SM_WHH 0u
#define SM_WHL 32768u
#define SM_WOH 65536u
#define SM_WOL 98304u
#define SM_WXH 131072u
#define SM_WXL 135168u
#define SM_TOTAL 139264u

// ---------------- global scratch (bf16 hi/lo splits) ----------------
__device__ __align__(16) bf16 g_h_hi[B_ * H_],  g_h_lo[B_ * H_];
__device__ __align__(16) bf16 g_x_hi[B_ * C_],  g_x_lo[B_ * C_];
__device__ __align__(16) bf16 g_xd_hi[B_ * C_], g_xd_lo[B_ * C_];
__device__ __align__(16) bf16 g_wh_hi[H_ * H_], g_wh_lo[H_ * H_];
__device__ __align__(16) bf16 g_wo_hi[H_ * H_], g_wo_lo[H_ * H_];
__device__ __align__(16) bf16 g_wx_hi[H_ * C_], g_wx_lo[H_ * C_];
__device__ __align__(16) bf16 g_relu_hi[B_ * H_], g_relu_lo[B_ * H_];
__device__ __align__(16) bf16 g_u_hi[B_ * H_],    g_u_lo[B_ * H_];
__device__ __align__(16) bf16 g_curr_hi[B_ * H_], g_curr_lo[B_ * H_];

// global barrier (prep only)
__device__ unsigned g_bar_count;
__device__ unsigned g_bar_gen;
// per-CTA monotonic produce flags, 128B padded
__device__ unsigned g_pflag[NROWG * RG_CTAS * 32];

extern __shared__ char smem[];

// ---------------- helpers ----------------
__device__ __forceinline__ uint32_t smem_u32(const void* p) {
    uint32_t a;
    asm("{ .reg .u64 t; cvta.to.shared.u64 t, %1; cvt.u32.u64 %0, t; }"
        : "=r"(a) : "l"(p));
    return a;
}
__device__ __forceinline__ uint32_t swz(int row, int u) {
    return (uint32_t)(row * 128 + ((u ^ (row & 7)) << 4));
}

#define CP_ASYNC16(sa, gp)                                                   \
    asm volatile("cp.async.cg.shared.global [%0], [%1], 16;"                 \
                 :: "r"((uint32_t)(sa)), "l"(gp))
#define CP_COMMIT() asm volatile("cp.async.commit_group;" ::: "memory")
#define CP_WAIT0()  asm volatile("cp.async.wait_group 0;" ::: "memory")

#define LDSM_X2(r, a)                                                        \
    asm volatile("ldmatrix.sync.aligned.m8n8.x2.shared.b16 {%0,%1}, [%2];"   \
                 : "=r"((r)[0]), "=r"((r)[1]) : "r"(a))
#define MMA_BF16(d, a, b)                                                    \
    asm volatile("mma.sync.aligned.m16n8k16.row.col.f32.bf16.bf16.f32 "      \
                 "{%0,%1,%2,%3}, {%4,%5,%6,%7}, {%8,%9}, {%0,%1,%2,%3};"     \
                 : "+f"((d)[0]), "+f"((d)[1]), "+f"((d)[2]), "+f"((d)[3])    \
                 : "r"((a)[0]), "r"((a)[1]), "r"((a)[2]), "r"((a)[3]),       \
                   "r"((b)[0]), "r"((b)[1]))

__device__ __forceinline__ unsigned ldcg_u32(const bf16* p) {
    return __ldcg((const unsigned*)p);
}

// global barrier (prep only; all 128 CTAs)
__device__ __forceinline__ void gbar(unsigned& gen) {
    __syncthreads();
    if (threadIdx.x == 0) {
        __threadfence();
        unsigned old = atomicAdd(&g_bar_count, 1);
        if (old == NCTA - 1) {
            g_bar_count = 0;
            __threadfence();
            atomicAdd(&g_bar_gen, 1);
        } else {
            while (*((volatile unsigned*)&g_bar_gen) == gen) { }
        }
        __threadfence();
        gen++;
    }
    __syncthreads();
}

// producer signal: all stores visible, then bump own flag
__device__ __forceinline__ void signal(int rg, int cy) {
    __threadfence();
    __syncthreads();
    if (threadIdx.x == 0)
        atomicAdd(&g_pflag[(rg * RG_CTAS + cy) * 32], 1u);
}

// wait until all 16 row-group flags reach tgt (warp-parallel poll; lanes 0..15)
__device__ __forceinline__ void wait_flags(int rg, unsigned tgt) {
    const int l = threadIdx.x & 31;
    if (l < RG_CTAS) {
        const unsigned* f = &g_pflag[(rg * RG_CTAS + l) * 32];
        unsigned v;
        do {
            asm volatile("ld.acquire.gpu.u32 %0, [%1];" : "=r"(v) : "l"(f));
        } while ((int)(v - tgt) < 0);
    }
    __syncwarp();
}

__device__ __forceinline__ void cvt_split(float v, bf16* hi, bf16* lo, int i) {
    bf16 h = __float2bfloat16(v);
    hi[i] = h;
    lo[i] = __float2bfloat16(v - __bfloat162float(h));
}

// store a pair (v0,v1) as hi/lo bf16x2 at element offset off (L2 path)
__device__ __forceinline__ void st_split_pair(bf16* hi, bf16* lo, size_t off,
                                              float v0, float v1) {
    bf16 h0 = __float2bfloat16(v0), h1 = __float2bfloat16(v1);
    unsigned uh = ((unsigned)__bfloat16_as_ushort(h1) << 16) |
                  (unsigned)__bfloat16_as_ushort(h0);
    bf16 l0 = __float2bfloat16(v0 - __bfloat162float(h0));
    bf16 l1 = __float2bfloat16(v1 - __bfloat162float(h1));
    unsigned ul = ((unsigned)__bfloat16_as_ushort(l1) << 16) |
                  (unsigned)__bfloat16_as_ushort(l0);
    __stcg((unsigned*)(hi + off), uh);
    __stcg((unsigned*)(lo + off), ul);
}

// ---------------------------------------------------------------------------
// Direct-load NT GEMM partial: A fragments ld.global.cg'd straight from the
// hi/lo activation buffers (no SMEM staging, no syncthreads). B from resident
// SMEM W tiles via ldsm. Accumulators split 3 terms x 2 chunk-parities:
//   acc[par*3+0] += Ahi*Whi, acc[par*3+1] += Alo*Whi, acc[par*3+2] += Ahi*Wlo
// m16n8k16 A-fragment positions per lane: a0=(r,c) a1=(r+8,c) a2=(r,c+8)
// a3=(r+8,c+8), r = mt*16 + (l>>2), c = ks*16 + (l&3)*2.
// ---------------------------------------------------------------------------
template <int NCH>
__device__ __forceinline__ void gemmG(const bf16* __restrict__ Ahi,
                                      const bf16* __restrict__ Alo,
                                      int strideA, int bm, uint32_t sb,
                                      uint32_t whi, uint32_t wlo,
                                      float (&acc)[6][4]) {
    const int tid = threadIdx.x;
    const int w = tid >> 5, l = tid & 31;
    const int mt = w >> 2, ng = w & 3;
    const int ra = bm + mt * 16 + (l >> 2);          // fragment row (a0/a2)
    const int cb = (l & 3) * 2;                      // fragment col base
    const int brow = ng * 8 + (l & 7), bsel = (l >> 3) & 1;
    const bf16* pa = Ahi + (size_t)ra * strideA + cb;
    const bf16* pl = Alo + (size_t)ra * strideA + cb;
    const size_t r8 = (size_t)8 * strideA;

#pragma unroll
    for (int c = 0; c < NCH; ++c) {
        const int par = (c & 1) * 3;
        const uint32_t whc = sb + whi + c * 4096u;
        const uint32_t wlc = sb + wlo + c * 4096u;
        // hoist B fragments for this chunk (resident SMEM, no dependencies)
        uint32_t bh[4][2], bl[4][2];
#pragma unroll
        for (int ks = 0; ks < 4; ++ks) {
            const uint32_t boff = swz(brow, ks * 2 + bsel);
            LDSM_X2(bh[ks], whc + boff);
            LDSM_X2(bl[ks], wlc + boff);
        }
        // A fragments for all 4 ks, loaded direct from L2 (32 independent LDG)
        uint32_t ah[4][4], al[4][4];
#pragma unroll
        for (int ks = 0; ks < 4; ++ks) {
            const int co = c * 64 + ks * 16;
            ah[ks][0] = ldcg_u32(pa + co);
            ah[ks][1] = ldcg_u32(pa + r8 + co);
            ah[ks][2] = ldcg_u32(pa + co + 8);
            ah[ks][3] = ldcg_u32(pa + r8 + co + 8);
            al[ks][0] = ldcg_u32(pl + co);
            al[ks][1] = ldcg_u32(pl + r8 + co);
            al[ks][2] = ldcg_u32(pl + co + 8);
            al[ks][3] = ldcg_u32(pl + r8 + co + 8);
        }
#pragma unroll
        for (int ks = 0; ks < 4; ++ks) {
            MMA_BF16(acc[par + 0], ah[ks], bh[ks]);
            MMA_BF16(acc[par + 1], al[ks], bh[ks]);
            MMA_BF16(acc[par + 2], ah[ks], bl[ks]);
        }
    }
}

__device__ __forceinline__ float fin(const float (&a)[6][4], int i) {
    return ((a[0][i] + a[3][i]) + (a[1][i] + a[4][i])) + (a[2][i] + a[5][i]);
}

// load one resident W slice (rows bn..bn+31, K as SW128 chunk tiles), cp.async
__device__ __forceinline__ void load_w(const bf16* __restrict__ src,
                                       uint32_t sb, uint32_t soff, int bn, int K) {
    const int tid = threadIdx.x;
    const int nu = (K / 64) * 32 * 8;
    for (int e = tid; e < nu; e += TPB) {
        int kc = e >> 8;
        int r = (e >> 3) & 31;
        int j = e & 7;
        CP_ASYNC16(sb + soff + kc * 4096 + swz(r, j),
                   src + (size_t)(bn + r) * K + kc * 64 + j * 8);
    }
}

// ---------------------------------------------------------------------------
__global__ void __launch_bounds__(TPB, 1) cde_kernel(
    const float* __restrict__ tptr, const float* __restrict__ tobs,
    const float* __restrict__ coeffs, const float* __restrict__ dcoeffs,
    const float* __restrict__ h, const float* __restrict__ wx,
    const float* __restrict__ wh, const float* __restrict__ wout,
    const float* __restrict__ b0, const float* __restrict__ b1,
    float* __restrict__ out) {
    const int tid = threadIdx.x;
    const int w = tid >> 5, l = tid & 31;
    const int mt = w >> 2, ng = w & 3;
    const int gid = l >> 2;
    const int rg = blockIdx.x;
    const int cy = blockIdx.y;
    const int bm = blockIdx.x * 32;
    const int bn = blockIdx.y * 32;
    const uint32_t sb = smem_u32(smem);

    __shared__ unsigned s_base;
    unsigned ggen = 0;
    if (tid == 0) {
        ggen = *((volatile unsigned*)&g_bar_gen);
        s_base = *((volatile unsigned*)&g_pflag[(rg * RG_CTAS + cy) * 32]);
    }

    // ---- Phase -1: spline + fp32 -> bf16 hi/lo splits (grid-flat) ----
    {
        const int gt = (blockIdx.y * gridDim.x + blockIdx.x) * TPB + tid;
        float tv = tptr[0];
        int idx = 0;
        for (int i = 0; i < NKNOTS; i++) idx += (tobs[i] <= tv) ? 1 : 0;
        idx = min(max(idx - 1, 0), NKNOTS - 2);
        const float dt = tv - tobs[idx];
        for (int i = gt; i < B_ * C_; i += GTH) {
            int b = i / C_, c = i % C_;
            size_t base = ((size_t)(b * (NKNOTS - 1) + idx)) * 4 * C_ + c;
            float v = coeffs[base] + dt * (coeffs[base + C_] +
                      dt * (coeffs[base + 2 * C_] + dt * coeffs[base + 3 * C_]));
            cvt_split(v, g_x_hi, g_x_lo, i);
            v = dcoeffs[base] + dt * (dcoeffs[base + C_] +
                dt * (dcoeffs[base + 2 * C_] + dt * dcoeffs[base + 3 * C_]));
            cvt_split(v, g_xd_hi, g_xd_lo, i);
        }
        for (int i = gt; i < B_ * H_; i += GTH) cvt_split(h[i], g_h_hi, g_h_lo, i);
        for (int i = gt; i < H_ * H_; i += GTH) cvt_split(wh[i], g_wh_hi, g_wh_lo, i);
        for (int i = gt; i < H_ * H_; i += GTH) cvt_split(wout[i], g_wo_hi, g_wo_lo, i);
        for (int i = gt; i < H_ * C_; i += GTH) cvt_split(wx[i], g_wx_hi, g_wx_lo, i);
    }
    gbar(ggen);   // only global barrier (prep visibility); also publishes s_base

    // ---- resident W tiles for this CTA's 32 cols ----
    load_w(g_wh_hi, sb, SM_WHH, bn, H_);
    load_w(g_wh_lo, sb, SM_WHL, bn, H_);
    load_w(g_wo_hi, sb, SM_WOH, bn, H_);
    load_w(g_wo_lo, sb, SM_WOL, bn, H_);
    load_w(g_wx_hi, sb, SM_WXH, bn, C_);
    load_w(g_wx_lo, sb, SM_WXL, bn, C_);
    CP_COMMIT();
    CP_WAIT0();
    __syncthreads();   // W tiles visible to all warps (once)

    const unsigned fbase = s_base;
    const int col0 = bn + ng * 8 + (l & 3) * 2;
    const float bc0 = b0[col0], bc1 = b0[col0 + 1];
    const float bz0 = b1[col0], bz1 = b1[col0 + 1];
    int rw[2];
    rw[0] = mt * 16 + gid;
    rw[1] = mt * 16 + 8 + gid;

    float sdr[4], sdt[4], hd[4];

    // ---- L1: acc = h@wh^T + x@wx^T ; aw = xdot@wx^T ----
    {
        float a[6][4] = {}, aw[6][4] = {};
        gemmG<8>(g_h_hi, g_h_lo, H_, bm, sb, SM_WHH, SM_WHL, a);
        gemmG<1>(g_x_hi, g_x_lo, C_, bm, sb, SM_WXH, SM_WXL, a);
        gemmG<1>(g_xd_hi, g_xd_lo, C_, bm, sb, SM_WXH, SM_WXL, aw);
#pragma unroll
        for (int p = 0; p < 2; ++p) {
            float v0 = fin(a, p * 2 + 0) + bc0;
            float v1 = fin(a, p * 2 + 1) + bc1;
            size_t off = (size_t)(bm + rw[p]) * H_ + col0;
            st_split_pair(g_relu_hi, g_relu_lo, off, fmaxf(v0, 0.f), fmaxf(v1, 0.f));
            float d0 = 1.0f / (1.0f + expf(-v0));
            float d1 = 1.0f / (1.0f + expf(-v1));
            sdr[p * 2] = d0;
            sdr[p * 2 + 1] = d1;
            st_split_pair(g_u_hi, g_u_lo, off,
                          d0 * fin(aw, p * 2), d1 * fin(aw, p * 2 + 1));
        }
    }
    signal(rg, cy);   // flag = base+1

    // ---- Z: z = relu@wout^T ; uq = u0@wout^T ----
    {
        wait_flags(rg, fbase + 1);
        float z[6][4] = {}, q[6][4] = {};
        gemmG<8>(g_relu_hi, g_relu_lo, H_, bm, sb, SM_WOH, SM_WOL, z);
        gemmG<8>(g_u_hi, g_u_lo, H_, bm, sb, SM_WOH, SM_WOL, q);
#pragma unroll
        for (int p = 0; p < 2; ++p) {
            float t0 = tanhf(fin(z, p * 2 + 0) + bz0);
            float t1 = tanhf(fin(z, p * 2 + 1) + bz1);
            float d0 = 1.0f - t0 * t0, d1 = 1.0f - t1 * t1;
            sdt[p * 2] = d0;
            sdt[p * 2 + 1] = d1;
            float v0 = d0 * fin(q, p * 2), v1 = d1 * fin(q, p * 2 + 1);
            hd[p * 2] = v0;
            hd[p * 2 + 1] = v1;
            size_t off = (size_t)(bm + rw[p]) * H_ + col0;
            st_split_pair(g_curr_hi, g_curr_lo, off, v0, v1);
        }
    }
    signal(rg, cy);   // flag = base+2

    // ---- 8 von-Neumann iterations ----
    for (int it = 0; it < KTERMS; ++it) {
        {   // u = drelu * (curr @ wh^T); curr produced at flag base+2+2it
            wait_flags(rg, fbase + 2 + 2 * it);
            float a[6][4] = {};
            gemmG<8>(g_curr_hi, g_curr_lo, H_, bm, sb, SM_WHH, SM_WHL, a);
#pragma unroll
            for (int p = 0; p < 2; ++p) {
                size_t off = (size_t)(bm + rw[p]) * H_ + col0;
                st_split_pair(g_u_hi, g_u_lo, off,
                              sdr[p * 2] * fin(a, p * 2),
                              sdr[p * 2 + 1] * fin(a, p * 2 + 1));
            }
        }
        signal(rg, cy);   // flag = base+3+2it
        {   // curr' = dtanh * (u @ wout^T); hdot += curr'
            wait_flags(rg, fbase + 3 + 2 * it);
            float c[6][4] = {};
            gemmG<8>(g_u_hi, g_u_lo, H_, bm, sb, SM_WOH, SM_WOL, c);
#pragma unroll
            for (int p = 0; p < 2; ++p) {
                float v0 = sdt[p * 2] * fin(c, p * 2);
                float v1 = sdt[p * 2 + 1] * fin(c, p * 2 + 1);
                hd[p * 2] += v0;
                hd[p * 2 + 1] += v1;
                if (it < KTERMS - 1) {
                    size_t off = (size_t)(bm + rw[p]) * H_ + col0;
                    st_split_pair(g_curr_hi, g_curr_lo, off, v0, v1);
                }
            }
            if (it < KTERMS - 1) signal(rg, cy);   // flag = base+4+2it
        }
    }

    // ---- write h_dot (fp32) ----
#pragma unroll
    for (int p = 0; p < 2; ++p) {
        size_t off = (size_t)(bm + rw[p]) * H_ + col0;
        *(float2*)(out + off) = make_float2(hd[p * 2], hd[p * 2 + 1]);
    }
}

// ---------------------------------------------------------------------------
extern "C" void kernel_launch(void* const* d_in, const int* in_sizes, int n_in,
                              void* d_out, int out_size) {
    const float* t      = (const float*)d_in[0];
    const float* h      = (const float*)d_in[1];
    const float* coeffs = (const float*)d_in[2];
    const float* dcoeff = (const float*)d_in[3];
    const float* tobs   = (const float*)d_in[4];
    const float* wx     = (const float*)d_in[5];
    const float* wh     = (const float*)d_in[6];
    const float* wout   = (const float*)d_in[7];
    const float* b0     = (const float*)d_in[8];
    const float* b1     = (const float*)d_in[9];
    float* out = (float*)d_out;

    cudaFuncSetAttribute(cde_kernel, cudaFuncAttributeMaxDynamicSharedMemorySize,
                         SM_TOTAL);
    dim3 grid(NROWG, RG_CTAS);  // 8 x 16 = 128 CTAs, single wave
    cde_kernel<<<grid, TPB, SM_TOTAL>>>(t, tobs, coeffs, dcoeff, h, wx, wh,
                                        wout, b0, b1, out);
}